// round 1
// baseline (speedup 1.0000x reference)
#include <cuda_runtime.h>
#include <math.h>

// Problem constants
#define B   8
#define HH  128
#define WW  128
#define NP  16384      // H*W
#define D   27         // PATCH*PATCH*C
#define NA  128        // number of anchors
#define AN  16         // anchors per block in main kernel
#define PCHUNKS 8
#define PCHUNK  (NP / PCHUNKS)   // 2048
#define TPB 256

// Scratch (device globals; no allocation allowed)
__device__ float g_pnT[B * D * NP];            // [b][d][p]  normalized patches, transposed
__device__ float g_posPart[B * NA * PCHUNKS];  // partial pos sums per p-chunk
__device__ float g_negPart[B * NA * PCHUNKS];  // partial neg sums per p-chunk
__device__ float g_cross[B * NA];              // cross sums

// ---------------------------------------------------------------------------
// Kernel 1: normalized 3x3 edge-padded patches -> g_pnT[b][d][p]
// ---------------------------------------------------------------------------
__global__ void patch_kernel(const float* __restrict__ lat)
{
    int idx = blockIdx.x * blockDim.x + threadIdx.x;
    if (idx >= B * NP) return;
    int b = idx >> 14;
    int p = idx & (NP - 1);
    int y = p >> 7;
    int x = p & 127;

    float v[D];
    float ss = 0.0f;
    int d = 0;
#pragma unroll
    for (int dy = -1; dy <= 1; dy++) {
        int yy = min(max(y + dy, 0), HH - 1);
#pragma unroll
        for (int dx = -1; dx <= 1; dx++) {
            int xx = min(max(x + dx, 0), WW - 1);
            const float* src = lat + (((size_t)(b * HH + yy) * WW + xx) * 3);
            float a0 = src[0], a1 = src[1], a2 = src[2];
            v[d] = a0; v[d + 1] = a1; v[d + 2] = a2;
            ss += a0 * a0 + a1 * a1 + a2 * a2;
            d += 3;
        }
    }
    float inv = 1.0f / fmaxf(sqrtf(ss), 1e-12f);
    float* dst = g_pnT + (size_t)b * D * NP + p;
#pragma unroll
    for (int k = 0; k < D; k++)
        dst[(size_t)k * NP] = v[k] * inv;
}

// ---------------------------------------------------------------------------
// Kernel 2: within-batch exp(dot) masked sums (pos / neg) per (b, anchor)
// grid: (PCHUNKS, NA/AN, B), block: 256
// ---------------------------------------------------------------------------
__global__ void __launch_bounds__(TPB, 2)
main_kernel(const int* __restrict__ aidx)
{
    int pc = blockIdx.x;
    int nt = blockIdx.y;
    int b  = blockIdx.z;
    int tid = threadIdx.x;

    __shared__ float sA[AN][D];
    __shared__ int   sAy[AN], sAx[AN];

    for (int t = tid; t < AN * D; t += TPB) {
        int a = t / D, d = t % D;
        int ai = aidx[nt * AN + a];
        sA[a][d] = g_pnT[((size_t)b * D + d) * NP + ai];
    }
    if (tid < AN) {
        int ai = aidx[nt * AN + tid];
        sAy[tid] = ai >> 7;
        sAx[tid] = ai & 127;
    }
    __syncthreads();

    float pos[AN], neg[AN];
#pragma unroll
    for (int a = 0; a < AN; a++) { pos[a] = 0.0f; neg[a] = 0.0f; }

    const float* pb = g_pnT + (size_t)b * D * NP;
    int base = pc * PCHUNK;
    for (int pp = base + tid; pp < base + PCHUNK; pp += TPB) {
        float v[D];
#pragma unroll
        for (int d = 0; d < D; d++) v[d] = pb[(size_t)d * NP + pp];
        int py = pp >> 7, px = pp & 127;
#pragma unroll
        for (int a = 0; a < AN; a++) {
            int dy = py - sAy[a], dx = px - sAx[a];
            int d2 = dy * dy + dx * dx;
            float dot = 0.0f;
#pragma unroll
            for (int d = 0; d < D; d++) dot = fmaf(v[d], sA[a][d], dot);
            float e = __expf(dot);
            if (d2 > 0 && d2 <= 9) pos[a] += e;
            if (d2 > 121)          neg[a] += e;
        }
    }

    // Warp reduce each accumulator
#pragma unroll
    for (int a = 0; a < AN; a++) {
#pragma unroll
        for (int off = 16; off > 0; off >>= 1) {
            pos[a] += __shfl_xor_sync(0xffffffffu, pos[a], off);
            neg[a] += __shfl_xor_sync(0xffffffffu, neg[a], off);
        }
    }

    __shared__ float rP[AN][TPB / 32];
    __shared__ float rN[AN][TPB / 32];
    int wid = tid >> 5, lane = tid & 31;
    if (lane == 0) {
#pragma unroll
        for (int a = 0; a < AN; a++) { rP[a][wid] = pos[a]; rN[a][wid] = neg[a]; }
    }
    __syncthreads();

    if (tid < AN * 2) {
        int a = tid & (AN - 1);
        bool isNeg = tid >= AN;
        float s = 0.0f;
#pragma unroll
        for (int w = 0; w < TPB / 32; w++) s += isNeg ? rN[a][w] : rP[a][w];
        int n = nt * AN + a;
        if (isNeg) g_negPart[((size_t)b * NA + n) * PCHUNKS + pc] = s;
        else       g_posPart[((size_t)b * NA + n) * PCHUNKS + pc] = s;
    }
}

// ---------------------------------------------------------------------------
// Kernel 3: cross-batch term. grid (NA, B), 32 threads.
// cross[b][n] = sum_{k != b} sum_{p: d2<=4} exp(2 * dot(anchor[b][n], pn[k][p]))
// ---------------------------------------------------------------------------
__global__ void cross_kernel(const int* __restrict__ aidx)
{
    int n = blockIdx.x;
    int b = blockIdx.y;
    int lane = threadIdx.x;

    __shared__ float av[D];
    int ai = aidx[n];
    if (lane < D) av[lane] = g_pnT[((size_t)b * D + lane) * NP + ai];
    __syncthreads();

    int ay = ai >> 7, ax = ai & 127;

    // 13 offsets with dy*dy+dx*dx <= 4
    const int ody[13] = {-2,-1,-1,-1, 0, 0, 0, 0, 0, 1, 1, 1, 2};
    const int odx[13] = { 0,-1, 0, 1,-2,-1, 0, 1, 2,-1, 0, 1, 0};

    float s = 0.0f;
    for (int idx = lane; idx < 13 * B; idx += 32) {
        int o = idx >> 3;
        int k = idx & 7;
        if (k == b) continue;
        int y = ay + ody[o], x = ax + odx[o];
        if (y < 0 || y >= HH || x < 0 || x >= WW) continue;
        int p = (y << 7) | x;
        const float* pk = g_pnT + (size_t)k * D * NP + p;
        float dot = 0.0f;
#pragma unroll
        for (int d = 0; d < D; d++) dot = fmaf(av[d], pk[(size_t)d * NP], dot);
        s += __expf(2.0f * dot);
    }
#pragma unroll
    for (int off = 16; off > 0; off >>= 1)
        s += __shfl_xor_sync(0xffffffffu, s, off);
    if (lane == 0) g_cross[(size_t)b * NA + n] = s;
}

// ---------------------------------------------------------------------------
// Kernel 4: counts, per-(b,n) loss, global reduce. 1 block, 128 threads.
// ---------------------------------------------------------------------------
__global__ void final_kernel(const int* __restrict__ aidx, float* __restrict__ out)
{
    int n = threadIdx.x;  // 0..127
    int ai = aidx[n];
    int ay = ai >> 7, ax = ai & 127;

    int pcnt = 0, ccnt = 0, in11 = 0;
#pragma unroll
    for (int dy = -3; dy <= 3; dy++)
#pragma unroll
        for (int dx = -3; dx <= 3; dx++) {
            int d2 = dy * dy + dx * dx;
            int y = ay + dy, x = ax + dx;
            bool inb = (y >= 0 && y < HH && x >= 0 && x < WW);
            if (inb && d2 > 0 && d2 <= 9) pcnt++;
            if (inb && d2 <= 4) ccnt++;
        }
    for (int dy = -11; dy <= 11; dy++)
        for (int dx = -11; dx <= 11; dx++) {
            int d2 = dy * dy + dx * dx;
            int y = ay + dy, x = ax + dx;
            if (d2 <= 121 && y >= 0 && y < HH && x >= 0 && x < WW) in11++;
        }
    int ncnt = NP - in11;

    float tot = 0.0f;
    int nv = 0;
    for (int b = 0; b < B; b++) {
        float ps = 0.0f, ns = 0.0f;
#pragma unroll
        for (int pc = 0; pc < PCHUNKS; pc++) {
            ps += g_posPart[((size_t)b * NA + n) * PCHUNKS + pc];
            ns += g_negPart[((size_t)b * NA + n) * PCHUNKS + pc];
        }
        float pm = (pcnt > 0) ? ps / (float)max(pcnt, 1) : 1.0f;
        float nm = ns / (float)max(ncnt, 1);
        float cm = g_cross[(size_t)b * NA + n] / (float)max((B - 1) * ccnt, 1);
        float lw = -logf(pm / (pm + nm + 1e-8f));
        float la = -logf(pm / (pm + cm + 1e-8f));
        float per = (ncnt > 0 ? lw : 0.0f) + (ccnt > 0 ? la : 0.0f);
        if (pcnt > 0 && (ncnt > 0 || ccnt > 0)) { tot += per; nv++; }
    }

    __shared__ float sT[NA];
    __shared__ int   sV[NA];
    sT[n] = tot; sV[n] = nv;
    __syncthreads();
    for (int s = NA / 2; s > 0; s >>= 1) {
        if (n < s) { sT[n] += sT[n + s]; sV[n] += sV[n + s]; }
        __syncthreads();
    }
    if (n == 0) out[0] = (sV[0] > 0) ? sT[0] / (float)sV[0] : 0.0f;
}

// ---------------------------------------------------------------------------
extern "C" void kernel_launch(void* const* d_in, const int* in_sizes, int n_in,
                              void* d_out, int out_size)
{
    const float* latents = (const float*)d_in[0];
    const int*   aidx    = (const int*)d_in[1];
    float*       out     = (float*)d_out;

    (void)in_sizes; (void)n_in; (void)out_size;

    patch_kernel<<<(B * NP + 255) / 256, 256>>>(latents);

    dim3 g2(PCHUNKS, NA / AN, B);
    main_kernel<<<g2, TPB>>>(aidx);

    dim3 g3(NA, B);
    cross_kernel<<<g3, 32>>>(aidx);

    final_kernel<<<1, NA>>>(aidx, out);
}

// round 3
// speedup vs baseline: 3.7169x; 3.7169x over previous
#include <cuda_runtime.h>
#include <math.h>

// Problem constants
#define B    8
#define HH   128
#define WW   128
#define NP   16384        // H*W
#define D    27           // PATCH*PATCH*C
#define DP   28           // padded to float4 multiple
#define NA   128          // number of anchors
#define AG   8            // anchors per group (main kernel)
#define NG   (NA / AG)    // 16 anchor groups
#define PC   16           // p-chunks
#define PCHUNK (NP / PC)  // 1024 pixels per chunk
#define TPB  256

// Scratch (device globals)
__device__ float g_pnT[B * DP * NP];          // [b][d][p] normalized patches (row 27 = 0)
__device__ float g_sumPart[B * NA * PC];      // total exp-sum partials per p-chunk
__device__ float g_pos[B * NA];               // pos exp-sums
__device__ float g_in121[B * NA];             // exp-sums over d2<=121 window
__device__ float g_cross[B * NA];             // cross exp-sums
__device__ int   g_cnt[NA * 3];               // per-anchor: pcnt, ccnt, c121

// ---------------------------------------------------------------------------
// Kernel 1: normalized 3x3 edge-padded patches -> g_pnT[b][d][p]
// ---------------------------------------------------------------------------
__global__ void patch_kernel(const float* __restrict__ lat)
{
    int idx = blockIdx.x * blockDim.x + threadIdx.x;
    if (idx >= B * NP) return;
    int b = idx >> 14;
    int p = idx & (NP - 1);
    int y = p >> 7;
    int x = p & 127;

    float v[D];
    float ss = 0.0f;
    int d = 0;
#pragma unroll
    for (int dy = -1; dy <= 1; dy++) {
        int yy = min(max(y + dy, 0), HH - 1);
#pragma unroll
        for (int dx = -1; dx <= 1; dx++) {
            int xx = min(max(x + dx, 0), WW - 1);
            const float* src = lat + (((size_t)(b * HH + yy) * WW + xx) * 3);
            float a0 = src[0], a1 = src[1], a2 = src[2];
            v[d] = a0; v[d + 1] = a1; v[d + 2] = a2;
            ss += a0 * a0 + a1 * a1 + a2 * a2;
            d += 3;
        }
    }
    float inv = 1.0f / fmaxf(sqrtf(ss), 1e-12f);
    float* dst = g_pnT + (size_t)b * DP * NP + p;
#pragma unroll
    for (int k = 0; k < DP; k++)
        dst[(size_t)k * NP] = (k < D) ? v[k] * inv : 0.0f;
}

// ---------------------------------------------------------------------------
// Kernel 2: UNMASKED total exp-sums. grid (PC, NG, B), block 256.
// Each thread: 4 consecutive pixels x 8 anchors; float4 loads everywhere.
// ---------------------------------------------------------------------------
__global__ void __launch_bounds__(TPB)
main_kernel(const int* __restrict__ aidx)
{
    int pc = blockIdx.x;
    int nt = blockIdx.y;
    int b  = blockIdx.z;
    int tid = threadIdx.x;

    __shared__ float sA[AG][DP];   // anchor vectors (row-padded, 16B-aligned rows)
    __shared__ float rS[AG][TPB / 32];

    for (int t = tid; t < AG * DP; t += TPB) {
        int a = t / DP, d = t % DP;
        int ai = aidx[nt * AG + a];
        sA[a][d] = g_pnT[((size_t)b * DP + d) * NP + ai];   // pad row is 0
    }
    __syncthreads();

    const float* pb = g_pnT + (size_t)b * DP * NP;
    int p0 = pc * PCHUNK + tid * 4;

    float dot[AG][4];
#pragma unroll
    for (int a = 0; a < AG; a++)
#pragma unroll
        for (int l = 0; l < 4; l++) dot[a][l] = 0.0f;

#pragma unroll
    for (int g = 0; g < DP / 4; g++) {
        float v[4][4];
#pragma unroll
        for (int j = 0; j < 4; j++) {
            float4 t4 = *reinterpret_cast<const float4*>(pb + (size_t)(g * 4 + j) * NP + p0);
            v[j][0] = t4.x; v[j][1] = t4.y; v[j][2] = t4.z; v[j][3] = t4.w;
        }
#pragma unroll
        for (int a = 0; a < AG; a++) {
            float4 w = *reinterpret_cast<const float4*>(&sA[a][g * 4]);
#pragma unroll
            for (int l = 0; l < 4; l++) {
                dot[a][l] = fmaf(v[0][l], w.x,
                            fmaf(v[1][l], w.y,
                            fmaf(v[2][l], w.z,
                            fmaf(v[3][l], w.w, dot[a][l]))));
            }
        }
    }

    float s[AG];
#pragma unroll
    for (int a = 0; a < AG; a++) {
        s[a] = __expf(dot[a][0]) + __expf(dot[a][1])
             + __expf(dot[a][2]) + __expf(dot[a][3]);
#pragma unroll
        for (int off = 16; off > 0; off >>= 1)
            s[a] += __shfl_xor_sync(0xffffffffu, s[a], off);
    }

    int wid = tid >> 5, lane = tid & 31;
    if (lane == 0) {
#pragma unroll
        for (int a = 0; a < AG; a++) rS[a][wid] = s[a];
    }
    __syncthreads();

    if (tid < AG) {
        float t = 0.0f;
#pragma unroll
        for (int w = 0; w < TPB / 32; w++) t += rS[tid][w];
        int n = nt * AG + tid;
        g_sumPart[((size_t)b * NA + n) * PC + pc] = t;
    }
}

// ---------------------------------------------------------------------------
// Kernel 3: window terms (pos, in121, counts) + cross-batch term.
// grid (NA, B), block 128.
// ---------------------------------------------------------------------------
__global__ void window_kernel(const int* __restrict__ aidx)
{
    int n = blockIdx.x;
    int b = blockIdx.y;
    int tid = threadIdx.x;

    __shared__ float av[DP];
    int ai = aidx[n];
    if (tid < DP) av[tid] = g_pnT[((size_t)b * DP + tid) * NP + ai];
    __syncthreads();

    int ay = ai >> 7, ax = ai & 127;

    float pos = 0.0f, in121 = 0.0f, cross = 0.0f;
    int pcnt = 0, ccnt = 0, c121 = 0;

    // within-batch 23x23 window (d2 <= 121)
    for (int t = tid; t < 23 * 23; t += 128) {
        int dy = t / 23 - 11;
        int dx = t % 23 - 11;
        int d2 = dy * dy + dx * dx;
        int y = ay + dy, x = ax + dx;
        if (d2 <= 121 && y >= 0 && y < HH && x >= 0 && x < WW) {
            c121++;
            if (d2 > 0 && d2 <= 9) pcnt++;
            if (d2 <= 4) ccnt++;
            int p = (y << 7) | x;
            const float* pk = g_pnT + (size_t)b * DP * NP + p;
            float dot = 0.0f;
#pragma unroll
            for (int d = 0; d < D; d++) dot = fmaf(av[d], pk[(size_t)d * NP], dot);
            float e = __expf(dot);
            in121 += e;
            if (d2 > 0 && d2 <= 9) pos += e;
        }
    }

    // cross-batch: 13 offsets with d2 <= 4, other batches, T=0.5
    {
        const int ody[13] = {-2,-1,-1,-1, 0, 0, 0, 0, 0, 1, 1, 1, 2};
        const int odx[13] = { 0,-1, 0, 1,-2,-1, 0, 1, 2,-1, 0, 1, 0};
        if (tid < 13 * B) {
            int o = tid >> 3;
            int k = tid & 7;
            int y = ay + ody[o], x = ax + odx[o];
            if (k != b && y >= 0 && y < HH && x >= 0 && x < WW) {
                int p = (y << 7) | x;
                const float* pk = g_pnT + (size_t)k * DP * NP + p;
                float dot = 0.0f;
#pragma unroll
                for (int d = 0; d < D; d++) dot = fmaf(av[d], pk[(size_t)d * NP], dot);
                cross += __expf(2.0f * dot);
            }
        }
    }

    // block reduce (4 warps)
    __shared__ float rf[3][4];
    __shared__ int   ri[3][4];
#pragma unroll
    for (int off = 16; off > 0; off >>= 1) {
        pos   += __shfl_xor_sync(0xffffffffu, pos, off);
        in121 += __shfl_xor_sync(0xffffffffu, in121, off);
        cross += __shfl_xor_sync(0xffffffffu, cross, off);
        pcnt  += __shfl_xor_sync(0xffffffffu, pcnt, off);
        ccnt  += __shfl_xor_sync(0xffffffffu, ccnt, off);
        c121  += __shfl_xor_sync(0xffffffffu, c121, off);
    }
    int wid = tid >> 5, lane = tid & 31;
    if (lane == 0) {
        rf[0][wid] = pos; rf[1][wid] = in121; rf[2][wid] = cross;
        ri[0][wid] = pcnt; ri[1][wid] = ccnt; ri[2][wid] = c121;
    }
    __syncthreads();
    if (tid == 0) {
        float P = 0, I = 0, X = 0; int pc2 = 0, cc2 = 0, c12 = 0;
#pragma unroll
        for (int w = 0; w < 4; w++) {
            P += rf[0][w]; I += rf[1][w]; X += rf[2][w];
            pc2 += ri[0][w]; cc2 += ri[1][w]; c12 += ri[2][w];
        }
        g_pos  [(size_t)b * NA + n] = P;
        g_in121[(size_t)b * NA + n] = I;
        g_cross[(size_t)b * NA + n] = X;
        if (b == 0) {
            g_cnt[n * 3 + 0] = pc2;
            g_cnt[n * 3 + 1] = cc2;
            g_cnt[n * 3 + 2] = c12;
        }
    }
}

// ---------------------------------------------------------------------------
// Kernel 4: per-(b,n) loss + global reduce. 1 block, 128 threads.
// ---------------------------------------------------------------------------
__global__ void final_kernel(float* __restrict__ out)
{
    int n = threadIdx.x;  // 0..127

    int pcnt = g_cnt[n * 3 + 0];
    int ccnt = g_cnt[n * 3 + 1];
    int c121 = g_cnt[n * 3 + 2];
    int ncnt = NP - c121;

    float tot = 0.0f;
    int nv = 0;
#pragma unroll
    for (int b = 0; b < B; b++) {
        float tsum = 0.0f;
#pragma unroll
        for (int pc = 0; pc < PC; pc++)
            tsum += g_sumPart[((size_t)b * NA + n) * PC + pc];
        float ps = g_pos  [(size_t)b * NA + n];
        float ns = tsum - g_in121[(size_t)b * NA + n];
        float cs = g_cross[(size_t)b * NA + n];

        float pm = (pcnt > 0) ? ps / (float)max(pcnt, 1) : 1.0f;
        float nm = ns / (float)max(ncnt, 1);
        float cm = cs / (float)max((B - 1) * ccnt, 1);
        float lw = -__logf(pm / (pm + nm + 1e-8f));
        float la = -__logf(pm / (pm + cm + 1e-8f));
        float per = (ncnt > 0 ? lw : 0.0f) + (ccnt > 0 ? la : 0.0f);
        if (pcnt > 0 && (ncnt > 0 || ccnt > 0)) { tot += per; nv++; }
    }

    __shared__ float sT[NA];
    __shared__ int   sV[NA];
    sT[n] = tot; sV[n] = nv;
    __syncthreads();
    for (int s = NA / 2; s > 0; s >>= 1) {
        if (n < s) { sT[n] += sT[n + s]; sV[n] += sV[n + s]; }
        __syncthreads();
    }
    if (n == 0) out[0] = (sV[0] > 0) ? sT[0] / (float)sV[0] : 0.0f;
}

// ---------------------------------------------------------------------------
extern "C" void kernel_launch(void* const* d_in, const int* in_sizes, int n_in,
                              void* d_out, int out_size)
{
    const float* latents = (const float*)d_in[0];
    const int*   aidx    = (const int*)d_in[1];
    float*       out     = (float*)d_out;

    (void)in_sizes; (void)n_in; (void)out_size;

    patch_kernel<<<(B * NP + 255) / 256, 256>>>(latents);

    dim3 g2(PC, NG, B);
    main_kernel<<<g2, TPB>>>(aidx);

    dim3 g3(NA, B);
    window_kernel<<<g3, 128>>>(aidx);

    final_kernel<<<1, NA>>>(out);
}

// round 4
// speedup vs baseline: 4.2476x; 1.1428x over previous
#include <cuda_runtime.h>
#include <math.h>

// Problem constants
#define B    8
#define HH   128
#define WW   128
#define NP   16384        // H*W
#define D    27           // PATCH*PATCH*C
#define DP   28           // padded to float4 multiple
#define NA   128          // number of anchors
#define AG   16           // anchors per group (main kernel)
#define NG   (NA / AG)    // 8 anchor groups
#define PC   16           // p-chunks
#define PCHUNK (NP / PC)  // 1024 pixels per chunk
#define TPB  256

// Scratch (device globals)
__device__ float g_pnT[B * DP * NP];          // [b][d][p] normalized patches (row 27 = 0)
__device__ float g_sumPart[B * NA * PC];      // total exp-sum partials per p-chunk
__device__ float g_pos[B * NA];               // pos exp-sums
__device__ float g_in121[B * NA];             // exp-sums over d2<=121 window
__device__ float g_cross[B * NA];             // cross exp-sums
__device__ int   g_cnt[NA * 3];               // per-anchor: pcnt, ccnt, c121

// ---------------------------------------------------------------------------
// Kernel 1: normalized 3x3 edge-padded patches -> g_pnT[b][d][p]
// ---------------------------------------------------------------------------
__global__ void patch_kernel(const float* __restrict__ lat)
{
    int idx = blockIdx.x * blockDim.x + threadIdx.x;
    if (idx >= B * NP) return;
    int b = idx >> 14;
    int p = idx & (NP - 1);
    int y = p >> 7;
    int x = p & 127;

    float v[D];
    float ss = 0.0f;
    int d = 0;
#pragma unroll
    for (int dy = -1; dy <= 1; dy++) {
        int yy = min(max(y + dy, 0), HH - 1);
#pragma unroll
        for (int dx = -1; dx <= 1; dx++) {
            int xx = min(max(x + dx, 0), WW - 1);
            const float* src = lat + (((size_t)(b * HH + yy) * WW + xx) * 3);
            float a0 = src[0], a1 = src[1], a2 = src[2];
            v[d] = a0; v[d + 1] = a1; v[d + 2] = a2;
            ss += a0 * a0 + a1 * a1 + a2 * a2;
            d += 3;
        }
    }
    float inv = 1.0f / fmaxf(sqrtf(ss), 1e-12f);
    float* dst = g_pnT + (size_t)b * DP * NP + p;
#pragma unroll
    for (int k = 0; k < DP; k++)
        dst[(size_t)k * NP] = (k < D) ? v[k] * inv : 0.0f;
}

// ---------------------------------------------------------------------------
// Kernel 2: UNMASKED total exp-sums. grid (PC, NG, B), block 256.
// Each thread: 4 consecutive pixels x 16 anchors; float4 loads everywhere.
// ---------------------------------------------------------------------------
__global__ void __launch_bounds__(TPB, 2)
main_kernel(const int* __restrict__ aidx)
{
    int pc = blockIdx.x;
    int nt = blockIdx.y;
    int b  = blockIdx.z;
    int tid = threadIdx.x;

    __shared__ float sA[AG][DP];   // anchor vectors (28 floats = 112B rows, 16B aligned)
    __shared__ float rS[AG][TPB / 32];

    for (int t = tid; t < AG * DP; t += TPB) {
        int a = t / DP, d = t % DP;
        int ai = aidx[nt * AG + a];
        sA[a][d] = g_pnT[((size_t)b * DP + d) * NP + ai];   // pad row is 0
    }
    __syncthreads();

    const float* pb = g_pnT + (size_t)b * DP * NP;
    int p0 = pc * PCHUNK + tid * 4;

    float dot[AG][4];
#pragma unroll
    for (int a = 0; a < AG; a++)
#pragma unroll
        for (int l = 0; l < 4; l++) dot[a][l] = 0.0f;

#pragma unroll
    for (int g = 0; g < DP / 4; g++) {
        float v[4][4];
#pragma unroll
        for (int j = 0; j < 4; j++) {
            float4 t4 = *reinterpret_cast<const float4*>(pb + (size_t)(g * 4 + j) * NP + p0);
            v[j][0] = t4.x; v[j][1] = t4.y; v[j][2] = t4.z; v[j][3] = t4.w;
        }
#pragma unroll
        for (int a = 0; a < AG; a++) {
            float4 w = *reinterpret_cast<const float4*>(&sA[a][g * 4]);
#pragma unroll
            for (int l = 0; l < 4; l++) {
                dot[a][l] = fmaf(v[0][l], w.x,
                            fmaf(v[1][l], w.y,
                            fmaf(v[2][l], w.z,
                            fmaf(v[3][l], w.w, dot[a][l]))));
            }
        }
    }

    float s[AG];
#pragma unroll
    for (int a = 0; a < AG; a++) {
        s[a] = __expf(dot[a][0]) + __expf(dot[a][1])
             + __expf(dot[a][2]) + __expf(dot[a][3]);
#pragma unroll
        for (int off = 16; off > 0; off >>= 1)
            s[a] += __shfl_xor_sync(0xffffffffu, s[a], off);
    }

    int wid = tid >> 5, lane = tid & 31;
    if (lane == 0) {
#pragma unroll
        for (int a = 0; a < AG; a++) rS[a][wid] = s[a];
    }
    __syncthreads();

    if (tid < AG) {
        float t = 0.0f;
#pragma unroll
        for (int w = 0; w < TPB / 32; w++) t += rS[tid][w];
        int n = nt * AG + tid;
        g_sumPart[((size_t)b * NA + n) * PC + pc] = t;
    }
}

// ---------------------------------------------------------------------------
// Kernel 3: window terms (pos, in121, counts) + cross-batch term.
// grid (NA, B), block 128.
// ---------------------------------------------------------------------------
__global__ void window_kernel(const int* __restrict__ aidx)
{
    int n = blockIdx.x;
    int b = blockIdx.y;
    int tid = threadIdx.x;

    __shared__ float av[DP];
    int ai = aidx[n];
    if (tid < DP) av[tid] = g_pnT[((size_t)b * DP + tid) * NP + ai];
    __syncthreads();

    int ay = ai >> 7, ax = ai & 127;

    float pos = 0.0f, in121 = 0.0f, cross = 0.0f;
    int pcnt = 0, ccnt = 0, c121 = 0;

    // within-batch 23x23 window (d2 <= 121)
    for (int t = tid; t < 23 * 23; t += 128) {
        int dy = t / 23 - 11;
        int dx = t % 23 - 11;
        int d2 = dy * dy + dx * dx;
        int y = ay + dy, x = ax + dx;
        if (d2 <= 121 && y >= 0 && y < HH && x >= 0 && x < WW) {
            c121++;
            if (d2 > 0 && d2 <= 9) pcnt++;
            if (d2 <= 4) ccnt++;
            int p = (y << 7) | x;
            const float* pk = g_pnT + (size_t)b * DP * NP + p;
            float dot = 0.0f;
#pragma unroll
            for (int d = 0; d < D; d++) dot = fmaf(av[d], pk[(size_t)d * NP], dot);
            float e = __expf(dot);
            in121 += e;
            if (d2 > 0 && d2 <= 9) pos += e;
        }
    }

    // cross-batch: 13 offsets with d2 <= 4, other batches, T=0.5
    {
        const int ody[13] = {-2,-1,-1,-1, 0, 0, 0, 0, 0, 1, 1, 1, 2};
        const int odx[13] = { 0,-1, 0, 1,-2,-1, 0, 1, 2,-1, 0, 1, 0};
        if (tid < 13 * B) {
            int o = tid >> 3;
            int k = tid & 7;
            int y = ay + ody[o], x = ax + odx[o];
            if (k != b && y >= 0 && y < HH && x >= 0 && x < WW) {
                int p = (y << 7) | x;
                const float* pk = g_pnT + (size_t)k * DP * NP + p;
                float dot = 0.0f;
#pragma unroll
                for (int d = 0; d < D; d++) dot = fmaf(av[d], pk[(size_t)d * NP], dot);
                cross += __expf(2.0f * dot);
            }
        }
    }

    // block reduce (4 warps)
    __shared__ float rf[3][4];
    __shared__ int   ri[3][4];
#pragma unroll
    for (int off = 16; off > 0; off >>= 1) {
        pos   += __shfl_xor_sync(0xffffffffu, pos, off);
        in121 += __shfl_xor_sync(0xffffffffu, in121, off);
        cross += __shfl_xor_sync(0xffffffffu, cross, off);
        pcnt  += __shfl_xor_sync(0xffffffffu, pcnt, off);
        ccnt  += __shfl_xor_sync(0xffffffffu, ccnt, off);
        c121  += __shfl_xor_sync(0xffffffffu, c121, off);
    }
    int wid = tid >> 5, lane = tid & 31;
    if (lane == 0) {
        rf[0][wid] = pos; rf[1][wid] = in121; rf[2][wid] = cross;
        ri[0][wid] = pcnt; ri[1][wid] = ccnt; ri[2][wid] = c121;
    }
    __syncthreads();
    if (tid == 0) {
        float P = 0, I = 0, X = 0; int pc2 = 0, cc2 = 0, c12 = 0;
#pragma unroll
        for (int w = 0; w < 4; w++) {
            P += rf[0][w]; I += rf[1][w]; X += rf[2][w];
            pc2 += ri[0][w]; cc2 += ri[1][w]; c12 += ri[2][w];
        }
        g_pos  [(size_t)b * NA + n] = P;
        g_in121[(size_t)b * NA + n] = I;
        g_cross[(size_t)b * NA + n] = X;
        if (b == 0) {
            g_cnt[n * 3 + 0] = pc2;
            g_cnt[n * 3 + 1] = cc2;
            g_cnt[n * 3 + 2] = c12;
        }
    }
}

// ---------------------------------------------------------------------------
// Kernel 4: per-(b,n) loss + global reduce. 1 block, 1024 threads
// (one thread per (b, n) pair).
// ---------------------------------------------------------------------------
__global__ void __launch_bounds__(1024)
final_kernel(float* __restrict__ out)
{
    int t = threadIdx.x;       // 0..1023
    int b = t >> 7;            // 0..7
    int n = t & 127;           // 0..127

    int pcnt = g_cnt[n * 3 + 0];
    int ccnt = g_cnt[n * 3 + 1];
    int c121 = g_cnt[n * 3 + 2];
    int ncnt = NP - c121;

    // sum the 16 p-chunk partials (contiguous, 64B aligned) via float4
    const float4* sp = reinterpret_cast<const float4*>(
        g_sumPart + ((size_t)b * NA + n) * PC);
    float tsum = 0.0f;
#pragma unroll
    for (int i = 0; i < PC / 4; i++) {
        float4 q = sp[i];
        tsum += q.x + q.y + q.z + q.w;
    }

    float ps = g_pos  [(size_t)b * NA + n];
    float ns = tsum - g_in121[(size_t)b * NA + n];
    float cs = g_cross[(size_t)b * NA + n];

    float pm = (pcnt > 0) ? ps / (float)max(pcnt, 1) : 1.0f;
    float nm = ns / (float)max(ncnt, 1);
    float cm = cs / (float)max((B - 1) * ccnt, 1);
    float lw = -__logf(pm / (pm + nm + 1e-8f));
    float la = -__logf(pm / (pm + cm + 1e-8f));
    float per = (ncnt > 0 ? lw : 0.0f) + (ccnt > 0 ? la : 0.0f);

    bool valid = (pcnt > 0) && (ncnt > 0 || ccnt > 0);
    float tot = valid ? per : 0.0f;
    int   nv  = valid ? 1 : 0;

    // block reduce 1024 -> 1
    __shared__ float sT[1024];
    __shared__ int   sV[1024];
    sT[t] = tot; sV[t] = nv;
    __syncthreads();
    for (int s = 512; s > 0; s >>= 1) {
        if (t < s) { sT[t] += sT[t + s]; sV[t] += sV[t + s]; }
        __syncthreads();
    }
    if (t == 0) out[0] = (sV[0] > 0) ? sT[0] / (float)sV[0] : 0.0f;
}

// ---------------------------------------------------------------------------
extern "C" void kernel_launch(void* const* d_in, const int* in_sizes, int n_in,
                              void* d_out, int out_size)
{
    const float* latents = (const float*)d_in[0];
    const int*   aidx    = (const int*)d_in[1];
    float*       out     = (float*)d_out;

    (void)in_sizes; (void)n_in; (void)out_size;

    patch_kernel<<<(B * NP + 255) / 256, 256>>>(latents);

    dim3 g2(PC, NG, B);
    main_kernel<<<g2, TPB>>>(aidx);

    dim3 g3(NA, B);
    window_kernel<<<g3, 128>>>(aidx);

    final_kernel<<<1, 1024>>>(out);
}

// round 7
// speedup vs baseline: 4.3922x; 1.0340x over previous
#include <cuda_runtime.h>
#include <math.h>

// Problem constants
#define B    8
#define HH   128
#define WW   128
#define NP   16384        // H*W
#define D    27           // PATCH*PATCH*C
#define DP   28           // padded to float4 multiple
#define NA   128          // number of anchors
#define AG   16           // anchors per group (main kernel)
#define NG   (NA / AG)    // 8 anchor groups
#define PC   16           // p-chunks
#define PCHUNK (NP / PC)  // 1024 pixels per chunk
#define TPB  256

// Packed f32x2 FMA: d(2xf32) += a(2xf32) * b(2xf32), single FFMA2 issue.
#define FMA2(d, a, b) \
    asm("fma.rn.f32x2 %0, %1, %2, %0;" : "+l"(d) : "l"(a), "l"(b))

// Scratch (device globals)
__device__ float g_pnT[B * DP * NP];          // [b][d][p] (pad row 27 = 0) for main kernel
__device__ float g_pn [B * NP * DP];          // [b][p][d] (pad col 27 = 0) for window/cross
__device__ float g_sumPart[B * NA * PC];      // total exp-sum partials per p-chunk
__device__ float g_pos[B * NA];               // pos exp-sums
__device__ float g_in121[B * NA];             // exp-sums over d2<=121 window
__device__ float g_cross[B * NA];             // cross exp-sums
__device__ int   g_cnt[NA * 3];               // per-anchor: pcnt, ccnt, c121

// ---------------------------------------------------------------------------
// Kernel 1: normalized 3x3 edge-padded patches -> g_pnT (d-major) + g_pn (p-major)
// ---------------------------------------------------------------------------
__global__ void patch_kernel(const float* __restrict__ lat)
{
    int idx = blockIdx.x * blockDim.x + threadIdx.x;
    if (idx >= B * NP) return;
    int b = idx >> 14;
    int p = idx & (NP - 1);
    int y = p >> 7;
    int x = p & 127;

    float v[DP];
    float ss = 0.0f;
    int d = 0;
#pragma unroll
    for (int dy = -1; dy <= 1; dy++) {
        int yy = min(max(y + dy, 0), HH - 1);
#pragma unroll
        for (int dx = -1; dx <= 1; dx++) {
            int xx = min(max(x + dx, 0), WW - 1);
            const float* src = lat + (((size_t)(b * HH + yy) * WW + xx) * 3);
            float a0 = src[0], a1 = src[1], a2 = src[2];
            v[d] = a0; v[d + 1] = a1; v[d + 2] = a2;
            ss += a0 * a0 + a1 * a1 + a2 * a2;
            d += 3;
        }
    }
    float inv = 1.0f / fmaxf(sqrtf(ss), 1e-12f);
#pragma unroll
    for (int k = 0; k < D; k++) v[k] *= inv;
    v[D] = 0.0f;

    // d-major copy (strided stores, coalesced per d)
    float* dstT = g_pnT + (size_t)b * DP * NP + p;
#pragma unroll
    for (int k = 0; k < DP; k++)
        dstT[(size_t)k * NP] = v[k];

    // p-major copy (7 x float4, contiguous; base is 112B = 7*16B aligned)
    float4* dstP = reinterpret_cast<float4*>(g_pn + ((size_t)b * NP + p) * DP);
#pragma unroll
    for (int k = 0; k < DP / 4; k++)
        dstP[k] = make_float4(v[4 * k], v[4 * k + 1], v[4 * k + 2], v[4 * k + 3]);
}

// ---------------------------------------------------------------------------
// Kernel 2: UNMASKED total exp-sums via packed FFMA2.
// grid (PC, NG, B), block 256. Each thread: 4 pixels x 16 anchors.
// Pixel lanes (p0,p1) and (p2,p3) live in packed 64-bit regs straight from
// LDG.128; anchor values are pre-duplicated (w,w) in shared.
// ---------------------------------------------------------------------------
__global__ void __launch_bounds__(TPB, 2)
main_kernel(const int* __restrict__ aidx)
{
    int pc = blockIdx.x;
    int nt = blockIdx.y;
    int b  = blockIdx.z;
    int tid = threadIdx.x;

    __shared__ float2 sA2[AG][DP];   // duplicated anchor values; row = 224B (16B mult.)
    __shared__ float rS[AG][TPB / 32];

    for (int t = tid; t < AG * DP; t += TPB) {
        int a = t / DP, d = t % DP;
        int ai = aidx[nt * AG + a];
        float w = g_pn[((size_t)b * NP + ai) * DP + d];   // pad col is 0
        sA2[a][d] = make_float2(w, w);
    }
    __syncthreads();

    const float* pb = g_pnT + (size_t)b * DP * NP;
    int p0 = pc * PCHUNK + tid * 4;

    unsigned long long acc0[AG], acc1[AG];   // packed (lane0,lane1), (lane2,lane3)
#pragma unroll
    for (int a = 0; a < AG; a++) { acc0[a] = 0ull; acc1[a] = 0ull; }

#pragma unroll
    for (int g = 0; g < DP / 4; g++) {
        ulonglong2 v[4];
#pragma unroll
        for (int j = 0; j < 4; j++)
            v[j] = *reinterpret_cast<const ulonglong2*>(pb + (size_t)(g * 4 + j) * NP + p0);
#pragma unroll
        for (int a = 0; a < AG; a++) {
            ulonglong2 w01 = *reinterpret_cast<const ulonglong2*>(&sA2[a][g * 4]);
            ulonglong2 w23 = *reinterpret_cast<const ulonglong2*>(&sA2[a][g * 4 + 2]);
            FMA2(acc0[a], v[0].x, w01.x); FMA2(acc1[a], v[0].y, w01.x);
            FMA2(acc0[a], v[1].x, w01.y); FMA2(acc1[a], v[1].y, w01.y);
            FMA2(acc0[a], v[2].x, w23.x); FMA2(acc1[a], v[2].y, w23.x);
            FMA2(acc0[a], v[3].x, w23.y); FMA2(acc1[a], v[3].y, w23.y);
        }
    }

    float s[AG];
#pragma unroll
    for (int a = 0; a < AG; a++) {
        float d0, d1, d2, d3;
        asm("mov.b64 {%0,%1}, %2;" : "=f"(d0), "=f"(d1) : "l"(acc0[a]));
        asm("mov.b64 {%0,%1}, %2;" : "=f"(d2), "=f"(d3) : "l"(acc1[a]));
        s[a] = __expf(d0) + __expf(d1) + __expf(d2) + __expf(d3);
#pragma unroll
        for (int off = 16; off > 0; off >>= 1)
            s[a] += __shfl_xor_sync(0xffffffffu, s[a], off);
    }

    int wid = tid >> 5, lane = tid & 31;
    if (lane == 0) {
#pragma unroll
        for (int a = 0; a < AG; a++) rS[a][wid] = s[a];
    }
    __syncthreads();

    if (tid < AG) {
        float t = 0.0f;
#pragma unroll
        for (int w = 0; w < TPB / 32; w++) t += rS[tid][w];
        int n = nt * AG + tid;
        g_sumPart[((size_t)b * NA + n) * PC + pc] = t;
    }
}

// ---------------------------------------------------------------------------
// Kernel 3: window terms (pos, in121, counts) + cross-batch term.
// grid (NA, B), block 128. Contiguous p-major reads (7 x LDG.128 per point).
// ---------------------------------------------------------------------------
__device__ __forceinline__ float dot_pn(const float4* __restrict__ av,
                                        const float* __restrict__ pk)
{
    const float4* q = reinterpret_cast<const float4*>(pk);
    float dot = 0.0f;
#pragma unroll
    for (int k = 0; k < DP / 4; k++) {
        float4 a = av[k], p = q[k];
        dot = fmaf(a.x, p.x, fmaf(a.y, p.y, fmaf(a.z, p.z, fmaf(a.w, p.w, dot))));
    }
    return dot;
}

__global__ void window_kernel(const int* __restrict__ aidx)
{
    int n = blockIdx.x;
    int b = blockIdx.y;
    int tid = threadIdx.x;

    int ai = aidx[n];
    float4 av[DP / 4];
    {
        const float4* src = reinterpret_cast<const float4*>(
            g_pn + ((size_t)b * NP + ai) * DP);
#pragma unroll
        for (int k = 0; k < DP / 4; k++) av[k] = src[k];
    }

    int ay = ai >> 7, ax = ai & 127;

    float pos = 0.0f, in121 = 0.0f, cross = 0.0f;
    int pcnt = 0, ccnt = 0, c121 = 0;

    // within-batch 23x23 window (d2 <= 121)
    for (int t = tid; t < 23 * 23; t += 128) {
        int dy = t / 23 - 11;
        int dx = t % 23 - 11;
        int d2 = dy * dy + dx * dx;
        int y = ay + dy, x = ax + dx;
        if (d2 <= 121 && y >= 0 && y < HH && x >= 0 && x < WW) {
            c121++;
            if (d2 > 0 && d2 <= 9) pcnt++;
            if (d2 <= 4) ccnt++;
            int p = (y << 7) | x;
            float dot = dot_pn(av, g_pn + ((size_t)b * NP + p) * DP);
            float e = __expf(dot);
            in121 += e;
            if (d2 > 0 && d2 <= 9) pos += e;
        }
    }

    // cross-batch: 13 offsets with d2 <= 4, other batches, T=0.5
    {
        const int ody[13] = {-2,-1,-1,-1, 0, 0, 0, 0, 0, 1, 1, 1, 2};
        const int odx[13] = { 0,-1, 0, 1,-2,-1, 0, 1, 2,-1, 0, 1, 0};
        if (tid < 13 * B) {
            int o = tid >> 3;
            int k = tid & 7;
            int y = ay + ody[o], x = ax + odx[o];
            if (k != b && y >= 0 && y < HH && x >= 0 && x < WW) {
                int p = (y << 7) | x;
                float dot = dot_pn(av, g_pn + ((size_t)k * NP + p) * DP);
                cross += __expf(2.0f * dot);
            }
        }
    }

    // block reduce (4 warps)
    __shared__ float rf[3][4];
    __shared__ int   ri[3][4];
#pragma unroll
    for (int off = 16; off > 0; off >>= 1) {
        pos   += __shfl_xor_sync(0xffffffffu, pos, off);
        in121 += __shfl_xor_sync(0xffffffffu, in121, off);
        cross += __shfl_xor_sync(0xffffffffu, cross, off);
        pcnt  += __shfl_xor_sync(0xffffffffu, pcnt, off);
        ccnt  += __shfl_xor_sync(0xffffffffu, ccnt, off);
        c121  += __shfl_xor_sync(0xffffffffu, c121, off);
    }
    int wid = tid >> 5, lane = tid & 31;
    if (lane == 0) {
        rf[0][wid] = pos; rf[1][wid] = in121; rf[2][wid] = cross;
        ri[0][wid] = pcnt; ri[1][wid] = ccnt; ri[2][wid] = c121;
    }
    __syncthreads();
    if (tid == 0) {
        float P = 0, I = 0, X = 0; int pc2 = 0, cc2 = 0, c12 = 0;
#pragma unroll
        for (int w = 0; w < 4; w++) {
            P += rf[0][w]; I += rf[1][w]; X += rf[2][w];
            pc2 += ri[0][w]; cc2 += ri[1][w]; c12 += ri[2][w];
        }
        g_pos  [(size_t)b * NA + n] = P;
        g_in121[(size_t)b * NA + n] = I;
        g_cross[(size_t)b * NA + n] = X;
        if (b == 0) {
            g_cnt[n * 3 + 0] = pc2;
            g_cnt[n * 3 + 1] = cc2;
            g_cnt[n * 3 + 2] = c12;
        }
    }
}

// ---------------------------------------------------------------------------
// Kernel 4: per-(b,n) loss + global reduce. 1 block, 1024 threads.
// ---------------------------------------------------------------------------
__global__ void __launch_bounds__(1024)
final_kernel(float* __restrict__ out)
{
    int t = threadIdx.x;       // 0..1023
    int b = t >> 7;            // 0..7
    int n = t & 127;           // 0..127

    int pcnt = g_cnt[n * 3 + 0];
    int ccnt = g_cnt[n * 3 + 1];
    int c121 = g_cnt[n * 3 + 2];
    int ncnt = NP - c121;

    const float4* sp = reinterpret_cast<const float4*>(
        g_sumPart + ((size_t)b * NA + n) * PC);
    float tsum = 0.0f;
#pragma unroll
    for (int i = 0; i < PC / 4; i++) {
        float4 q = sp[i];
        tsum += q.x + q.y + q.z + q.w;
    }

    float ps = g_pos  [(size_t)b * NA + n];
    float ns = tsum - g_in121[(size_t)b * NA + n];
    float cs = g_cross[(size_t)b * NA + n];

    float pm = (pcnt > 0) ? ps / (float)max(pcnt, 1) : 1.0f;
    float nm = ns / (float)max(ncnt, 1);
    float cm = cs / (float)max((B - 1) * ccnt, 1);
    float lw = -__logf(pm / (pm + nm + 1e-8f));
    float la = -__logf(pm / (pm + cm + 1e-8f));
    float per = (ncnt > 0 ? lw : 0.0f) + (ccnt > 0 ? la : 0.0f);

    bool valid = (pcnt > 0) && (ncnt > 0 || ccnt > 0);
    float tot = valid ? per : 0.0f;
    int   nv  = valid ? 1 : 0;

    __shared__ float sT[1024];
    __shared__ int   sV[1024];
    sT[t] = tot; sV[t] = nv;
    __syncthreads();
    for (int s = 512; s > 0; s >>= 1) {
        if (t < s) { sT[t] += sT[t + s]; sV[t] += sV[t + s]; }
        __syncthreads();
    }
    if (t == 0) out[0] = (sV[0] > 0) ? sT[0] / (float)sV[0] : 0.0f;
}

// ---------------------------------------------------------------------------
extern "C" void kernel_launch(void* const* d_in, const int* in_sizes, int n_in,
                              void* d_out, int out_size)
{
    const float* latents = (const float*)d_in[0];
    const int*   aidx    = (const int*)d_in[1];
    float*       out     = (float*)d_out;

    (void)in_sizes; (void)n_in; (void)out_size;

    patch_kernel<<<(B * NP + 255) / 256, 256>>>(latents);

    dim3 g2(PC, NG, B);
    main_kernel<<<g2, TPB>>>(aidx);

    dim3 g3(NA, B);
    window_kernel<<<g3, 128>>>(aidx);

    final_kernel<<<1, 1024>>>(out);
}